// round 16
// baseline (speedup 1.0000x reference)
#include <cuda_runtime.h>
#include <cuda_bf16.h>

// Shapes: A=1, B=8, M=256, H(=Kdim)=2048, E=8, K=2, N=2048
// out (scalar) = sum_{b,e,k} sp[b,e] * hsum[b,k] * wsum[e,k]
//   hsum[b,k] = sum_m hidden[0,b,m,k]     (16 MB stream)
//   wsum[e,k] = sum_n W[0,e,k,n]          (134 MB stream)
//
// R16: persistent single-wave streamer (1152 blocks x 2 uniform 64KB units,
// __ldcs evict-first so the 1.1 MB of partials stays L2-resident) +
// combine in R14's proven 64x256 shape but with ZERO contended atomics
// (smem block reduce -> plain slot store -> release ticket -> last block sums).

#define Bd 8
#define Md 256
#define Hd 2048
#define Ed 8
#define Nd 2048

#define W_UNITS    2048            // unit u<2048: 8 W rows (one per warp)
#define H_UNITS    256             // unit u>=2048: one 64KB hidden chunk
#define UNITS      (W_UNITS + H_UNITS)
#define S_BLOCKS   1152            // x2 units each, single wave (<=1184 resident)
#define MCHUNKS    16

#define C_BLOCKS   64              // combine: 64 blocks x 256 (R14 shape)

__device__ float  g_wsum[Ed * Hd];            // 64 KB
__device__ float  g_part[MCHUNKS * Bd * Hd];  // 1 MB partial hidden sums
__device__ double g_slots[C_BLOCKS];
__device__ unsigned int g_done;

__device__ __forceinline__ float4 ldcs4(const float4* p) {
    float4 v;
    asm volatile("ld.global.cs.v4.f32 {%0,%1,%2,%3}, [%4];"
                 : "=f"(v.x), "=f"(v.y), "=f"(v.z), "=f"(v.w) : "l"(p));
    return v;
}

// ---------------- kernel 1: all 150 MB of streaming, single wave ----------------
__global__ void __launch_bounds__(256) k_stream(const float* __restrict__ W,
                                                const float* __restrict__ hidden) {
    if (blockIdx.x == 0 && threadIdx.x == 0) g_done = 0u;

    const int warp = threadIdx.x >> 5;
    const int lane = threadIdx.x & 31;

#pragma unroll
    for (int half = 0; half < 2; half++) {
        int u = blockIdx.x + half * S_BLOCKS;        // 0..2303

        if (u < W_UNITS) {
            // ---- W row sums: one warp per row of 2048 floats ----
            int row = u * 8 + warp;                  // e*2048 + k
            const float4* src = reinterpret_cast<const float4*>(W + (size_t)row * Nd);
            float s = 0.f;
#pragma unroll
            for (int i = 0; i < 16; i++) {           // 16 f4 * 32 lanes = 2048 floats
                float4 v = ldcs4(src + lane + 32 * i);
                s += (v.x + v.y) + (v.z + v.w);
            }
#pragma unroll
            for (int off = 16; off > 0; off >>= 1)
                s += __shfl_xor_sync(0xffffffff, s, off);
            if (lane == 0) g_wsum[row] = s;
        } else {
            // ---- hidden partial column sums: 64 KB unit, plain stores ----
            int idx = u - W_UNITS;                   // 0..255
            int mc  = idx >> 4;                      // m chunk (0..15)
            int kb  = idx & 15;                      // k4 block (0..15)
            int g   = kb * 256 + threadIdx.x;        // 0..4095 = b*512 + k4
            int b   = g >> 9;
            int k4  = g & 511;
            int m0  = mc * 16;

            const float4* src = reinterpret_cast<const float4*>(
                hidden + (size_t)(b * Md + m0) * Hd) + k4;

            float4 acc = make_float4(0.f, 0.f, 0.f, 0.f);
#pragma unroll
            for (int i = 0; i < 16; i++) {
                float4 v = ldcs4(src + i * (Hd / 4));
                acc.x += v.x; acc.y += v.y; acc.z += v.z; acc.w += v.w;
            }
            reinterpret_cast<float4*>(g_part)[mc * 4096 + g] = acc;  // [c][b][k]
        }
    }

    asm volatile("griddepcontrol.launch_dependents;");
}

// ---------------- kernel 2: contraction, R14 shape, no contended atomics ----------------
// 64 blocks x 256; thread t owns (b = t>>11, k = t&2047).
__global__ void __launch_bounds__(256) k_combine(const float* __restrict__ sp,
                                                 float* __restrict__ out) {
    __shared__ double s_red[8];
    const int tid  = threadIdx.x;
    const int warp = tid >> 5;
    const int lane = tid & 31;

    int t = blockIdx.x * 256 + tid;                  // 0..16383
    int b = t >> 11;
    int k = t & 2047;

    float spc[Ed];                                   // prologue before wait
#pragma unroll
    for (int e = 0; e < Ed; e++)
        spc[e] = sp[b * 16 + e];                     // sp layout (b, K=2, e): slice 0

    asm volatile("griddepcontrol.wait;");            // no-op without PDL

    float hs = 0.f;                                  // 16 independent L2 loads
#pragma unroll
    for (int c = 0; c < MCHUNKS; c++)
        hs += __ldcg(&g_part[c * (Bd * Hd) + b * Hd + k]);

    float cb = 0.f;
#pragma unroll
    for (int e = 0; e < Ed; e++)
        cb += spc[e] * __ldcg(&g_wsum[e * Hd + k]);

    double acc = (double)hs * (double)cb;

    // block reduce: warp shuffle -> smem -> warp0; ONE plain store per block
#pragma unroll
    for (int off = 16; off > 0; off >>= 1)
        acc += __shfl_xor_sync(0xffffffff, acc, off);
    if (lane == 0) s_red[warp] = acc;
    __syncthreads();
    if (warp == 0) {
        double d = (lane < 8) ? s_red[lane] : 0.0;
#pragma unroll
        for (int off = 4; off > 0; off >>= 1)
            d += __shfl_xor_sync(0xffffffff, d, off);
        if (lane == 0) {
            g_slots[blockIdx.x] = d;                 // distinct address per block
            unsigned int tkt;
            asm volatile("atom.release.gpu.global.add.u32 %0, [%1], %2;"
                         : "=r"(tkt) : "l"(&g_done), "r"(1u) : "memory");
            if (tkt == C_BLOCKS - 1) {
                asm volatile("fence.acq_rel.gpu;" ::: "memory");
                double total = 0.0;
#pragma unroll
                for (int i = 0; i < C_BLOCKS; i++) total += g_slots[i];
                out[0] = (float)total;
            }
        }
    }
}

extern "C" void kernel_launch(void* const* d_in, const int* in_sizes, int n_in,
                              void* d_out, int out_size) {
    const float* hidden = (const float*)d_in[0];   // (1,8,256,2048)
    const float* sp     = (const float*)d_in[1];   // (1,8,2,8)
    const float* W      = (const float*)d_in[2];   // (1,8,2048,2048)
    float* out = (float*)d_out;

    k_stream<<<S_BLOCKS, 256>>>(W, hidden);

    cudaLaunchConfig_t cfg = {};
    cfg.gridDim  = dim3(C_BLOCKS, 1, 1);
    cfg.blockDim = dim3(256, 1, 1);
    cfg.dynamicSmemBytes = 0;
    cfg.stream = (cudaStream_t)0;
    cudaLaunchAttribute attr[1];
    attr[0].id = cudaLaunchAttributeProgrammaticStreamSerialization;
    attr[0].val.programmaticStreamSerializationAllowed = 1;
    cfg.attrs = attr;
    cfg.numAttrs = 1;

    cudaError_t err = cudaLaunchKernelEx(&cfg, k_combine, sp, out);
    if (err != cudaSuccess) {
        k_combine<<<C_BLOCKS, 256>>>(sp, out);       // fallback, still correct
    }
}